// round 5
// baseline (speedup 1.0000x reference)
#include <cuda_runtime.h>
#include <math.h>

// Problem constants (fixed by reference setup)
#define BD     16      // batch
#define HD     16      // heads
#define DD     128     // head dim
#define BLKD   16      // tokens per cache block
#define MAXBD  128     // blocks per sequence
#define MAXSD  2048    // max sequence length
#define NSPLIT 16      // token splits per batch
#define CHUNK  128     // tokens per split
#define SOFTMAX_SCALE 0.088388347648318447f  // 1/sqrt(128)
#define NEGBIG (-1e30f)

// Partial-result scratch (allocation-free: __device__ globals, zero-init .bss)
__device__ float g_pm[BD * HD * NSPLIT];
__device__ float g_pl[BD * HD * NSPLIT];
__device__ float g_pacc[BD * HD * NSPLIT * DD];      // 2 MB
__device__ unsigned int g_cnt[BD];                   // self-resetting counters

// ---- cp.async helpers -----------------------------------------------------
__device__ __forceinline__ void cp16(void* sptr, const void* gptr) {
    unsigned s = (unsigned)__cvta_generic_to_shared(sptr);
    asm volatile("cp.async.cg.shared.global [%0], [%1], 16;" :: "r"(s), "l"(gptr));
}
__device__ __forceinline__ void cp_commit() {
    asm volatile("cp.async.commit_group;");
}
template <int N> __device__ __forceinline__ void cp_wait() {
    asm volatile("cp.async.wait_group %0;" :: "n"(N));
}

// ---------------------------------------------------------------------------
// DRAM-streaming split-KV decode attention.
//  grid (NSPLIT, BD): CTA = (token split, batch). 512 threads = 16 warps,
//  warp w = head w. Per token the CTA stages the FULL 8KB K row + 8KB V row
//  (all 16 heads, contiguous in memory; consecutive tokens are adjacent rows
//  -> long contiguous DRAM streams) via cp.async into a 3-slot SMEM ring.
//  Each warp computes its head's online softmax from SMEM.
//  Per-warp partials go to global scratch; the last split CTA per batch
//  (threadfence reduction) combines 16 splits x 16 heads and writes out,
//  then resets the counter (graph-replay deterministic).
// ---------------------------------------------------------------------------
__global__ __launch_bounds__(512, 3) void attn_fused(
    const float* __restrict__ Q,  const float* __restrict__ K,
    const float* __restrict__ V,  const float* __restrict__ Kc,
    const float* __restrict__ Vc, const float* __restrict__ cosb,
    const float* __restrict__ sinb, const float* __restrict__ mask,
    const int* __restrict__ ilen, const int* __restrict__ btab,
    float* __restrict__ out)
{
    // ring: [slot][K/V][head][lane-float4] = 3*2*16*32*16B = 49152B (48KB)
    __shared__ float4 buf[3][2][HD][32];

    const int split = blockIdx.x, b = blockIdx.y;
    const int tid = threadIdx.x;
    const int h = tid >> 5, lane = tid & 31;   // warp == head
    const int L  = ilen[b];
    const int s0 = split * CHUNK;

    if (s0 < L) {
        const int ntok = (L - s0 < CHUNK) ? (L - s0) : CHUNK;
        const int pos  = L - 1;                 // fresh-token position
        const int bh   = b * HD + h;

        // --- RoPE on Q and K (registers, per-head per-warp) ---
        const float4 q4  = *(const float4*)(Q    + bh * DD + 4 * lane);
        const float4 k4  = *(const float4*)(K    + bh * DD + 4 * lane);
        const float4 vv4 = *(const float4*)(V    + bh * DD + 4 * lane);
        const float4 c4  = *(const float4*)(cosb + b * DD + 4 * lane);
        const float4 s4  = *(const float4*)(sinb + b * DD + 4 * lane);

        const float sgn = (lane < 16) ? -1.f : 1.f;   // rot = [-x2, x1]
        float4 qp, kp;
        qp.x = __shfl_xor_sync(~0u, q4.x, 16);  qp.y = __shfl_xor_sync(~0u, q4.y, 16);
        qp.z = __shfl_xor_sync(~0u, q4.z, 16);  qp.w = __shfl_xor_sync(~0u, q4.w, 16);
        kp.x = __shfl_xor_sync(~0u, k4.x, 16);  kp.y = __shfl_xor_sync(~0u, k4.y, 16);
        kp.z = __shfl_xor_sync(~0u, k4.z, 16);  kp.w = __shfl_xor_sync(~0u, k4.w, 16);

        float4 qr, kr;   // qr pre-scaled by softmax scale
        qr.x = (q4.x * c4.x + sgn * qp.x * s4.x) * SOFTMAX_SCALE;
        qr.y = (q4.y * c4.y + sgn * qp.y * s4.y) * SOFTMAX_SCALE;
        qr.z = (q4.z * c4.z + sgn * qp.z * s4.z) * SOFTMAX_SCALE;
        qr.w = (q4.w * c4.w + sgn * qp.w * s4.w) * SOFTMAX_SCALE;
        kr.x =  k4.x * c4.x + sgn * kp.x * s4.x;
        kr.y =  k4.y * c4.y + sgn * kp.y * s4.y;
        kr.z =  k4.z * c4.z + sgn * kp.z * s4.z;
        kr.w =  k4.w * c4.w + sgn * kp.w * s4.w;

        const int*   bt = btab + b * MAXBD;
        const float* mk = mask + b * MAXSD;

        // stage i: whole 8KB K row + 8KB V row of token s0+i (cooperative)
        auto issue = [&](int i) {
            if (i < ntok) {
                const int t   = s0 + i;
                const int row = __ldg(bt + (t >> 4)) * BLKD + (t & 15);
                const size_t base = (size_t)row * (HD * DD);
                const int slot = i % 3;
                cp16(&((float4*)buf[slot][0])[tid], (const float4*)(Kc + base) + tid);
                cp16(&((float4*)buf[slot][1])[tid], (const float4*)(Vc + base) + tid);
            }
            cp_commit();   // always commit (uniform group counting)
        };
        issue(0);
        issue(1);

        float m = NEGBIG, l = 0.f;
        float4 acc = make_float4(0.f, 0.f, 0.f, 0.f);

        for (int i = 0; i < ntok; i++) {
            cp_wait<1>();        // group i complete
            __syncthreads();     // data visible; everyone done with slot (i-1)%3
            issue(i + 2);        // overwrites slot (i-1)%3 -- safe after barrier

            const int slot = i % 3;
            const int t    = s0 + i;
            float4 kk = buf[slot][0][h][lane];
            float4 vv = buf[slot][1][h][lane];
            if (t == pos) { kk = kr; vv = vv4; }   // fresh token substitution

            float dot = qr.x * kk.x + qr.y * kk.y + qr.z * kk.z + qr.w * kk.w;
            #pragma unroll
            for (int o = 16; o > 0; o >>= 1)
                dot += __shfl_xor_sync(~0u, dot, o);

            const float score = dot + __ldg(mk + t);
            const float mnew  = fmaxf(m, score);
            const float corr  = __expf(m - mnew);
            const float p     = __expf(score - mnew);
            l = l * corr + p;
            acc.x = acc.x * corr + p * vv.x;
            acc.y = acc.y * corr + p * vv.y;
            acc.z = acc.z * corr + p * vv.z;
            acc.w = acc.w * corr + p * vv.w;
            m = mnew;
        }

        // per-warp partial straight to global scratch
        const int pidx = bh * NSPLIT + split;
        if (lane == 0) { g_pm[pidx] = m; g_pl[pidx] = l; }
        *(float4*)(g_pacc + pidx * DD + 4 * lane) = acc;
    } else {
        // empty split: neutral partials (one per head-warp)
        const int pidx = (b * HD + h) * NSPLIT + split;
        if (lane == 0) { g_pm[pidx] = NEGBIG; g_pl[pidx] = 0.f; }
        *(float4*)(g_pacc + pidx * DD + 4 * lane) = make_float4(0.f, 0.f, 0.f, 0.f);
    }

    // --- threadfence reduction: last split CTA for batch b combines ---
    unsigned* s_flag = (unsigned*)buf;   // buf dead past this point
    __threadfence();
    __syncthreads();
    if (tid == 0)
        *s_flag = (atomicAdd(&g_cnt[b], 1u) == NSPLIT - 1u) ? 1u : 0u;
    __syncthreads();

    if (*s_flag) {
        const int d = tid & 127;       // dim
        const int g = tid >> 7;        // 0..3 head group
        #pragma unroll
        for (int it = 0; it < 4; it++) {
            const int hh   = g * 4 + it;
            const int base = (b * HD + hh) * NSPLIT;

            float M = -INFINITY;
            #pragma unroll
            for (int i = 0; i < NSPLIT; i++)
                if (g_pl[base + i] > 0.f) M = fmaxf(M, g_pm[base + i]);

            float Lt = 0.f, a = 0.f;
            #pragma unroll
            for (int i = 0; i < NSPLIT; i++) {
                const float li = g_pl[base + i];
                if (li > 0.f) {
                    const float w = __expf(g_pm[base + i] - M);
                    Lt += w * li;
                    a  += w * g_pacc[(base + i) * DD + d];
                }
            }
            out[(b * HD + hh) * DD + d] = a / Lt;
        }
        if (tid == 0) g_cnt[b] = 0u;   // self-reset for next graph replay
    }
}

// ---------------------------------------------------------------------------
extern "C" void kernel_launch(void* const* d_in, const int* in_sizes, int n_in,
                              void* d_out, int out_size)
{
    const float* Q    = (const float*)d_in[0];
    const float* K    = (const float*)d_in[1];
    const float* V    = (const float*)d_in[2];
    const float* Kc   = (const float*)d_in[3];
    const float* Vc   = (const float*)d_in[4];
    const float* cosb = (const float*)d_in[5];
    const float* sinb = (const float*)d_in[6];
    const float* mask = (const float*)d_in[7];
    const int*   ilen = (const int*)d_in[8];
    // d_in[9] = save_slots — unused (fresh token is at input_length-1)
    const int*   btab = (const int*)d_in[10];
    (void)in_sizes; (void)n_in; (void)out_size;

    dim3 g1(NSPLIT, BD);
    attn_fused<<<g1, 512>>>(Q, K, V, Kc, Vc, cosb, sinb, mask, ilen, btab,
                            (float*)d_out);
}

// round 6
// speedup vs baseline: 1.2311x; 1.2311x over previous
#include <cuda_runtime.h>
#include <math.h>

// Problem constants (fixed by reference setup)
#define BD     16      // batch
#define HD     16      // heads
#define DD     128     // head dim
#define BLKD   16      // tokens per cache block
#define MAXBD  128     // blocks per sequence
#define MAXSD  2048    // max sequence length
#define NSPLIT 32      // token splits per batch
#define CHUNK  64      // tokens per split
#define NSLOT  4       // SMEM ring slots
#define SOFTMAX_SCALE 0.088388347648318447f  // 1/sqrt(128)
#define NEGBIG (-1e30f)

// SMEM: ring 4*2*16*32*16B = 64KB, + row cache + flag
#define SMEM_RING   (NSLOT * 2 * HD * 32 * 16)
#define SMEM_TOTAL  (SMEM_RING + 32)

// Partial-result scratch (allocation-free: __device__ globals, zero-init .bss)
__device__ float g_pm[BD * HD * NSPLIT];
__device__ float g_pl[BD * HD * NSPLIT];
__device__ float g_pacc[BD * HD * NSPLIT * DD];      // 4 MB
__device__ unsigned int g_cnt[BD];                   // self-resetting counters

// ---- cp.async helpers -----------------------------------------------------
__device__ __forceinline__ void cp16(void* sptr, const void* gptr) {
    unsigned s = (unsigned)__cvta_generic_to_shared(sptr);
    asm volatile("cp.async.cg.shared.global [%0], [%1], 16;" :: "r"(s), "l"(gptr));
}
__device__ __forceinline__ void cp_commit() {
    asm volatile("cp.async.commit_group;");
}
template <int N> __device__ __forceinline__ void cp_wait() {
    asm volatile("cp.async.wait_group %0;" :: "n"(N));
}

// ---------------------------------------------------------------------------
// DRAM-streaming split-KV decode attention.
//  grid (NSPLIT=32, BD): CTA = (token split of 64, batch). 512 threads =
//  16 warps, warp w = head w. Per token the CTA stages the FULL 8KB K row +
//  8KB V row (all heads, contiguous; consecutive tokens adjacent rows ->
//  long contiguous DRAM streams) via cp.async into a 4-slot SMEM ring with
//  TWO full stages always in flight (wait_group<2>).
//  Each warp runs its head's online softmax from SMEM.
//  Empty splits write nothing (combiner uses ceil(L/CHUNK)).
//  Last split CTA per batch (threadfence reduction) combines and writes out,
//  then resets the counter (graph-replay deterministic).
// ---------------------------------------------------------------------------
__global__ __launch_bounds__(512, 3) void attn_fused(
    const float* __restrict__ Q,  const float* __restrict__ K,
    const float* __restrict__ V,  const float* __restrict__ Kc,
    const float* __restrict__ Vc, const float* __restrict__ cosb,
    const float* __restrict__ sinb, const float* __restrict__ mask,
    const int* __restrict__ ilen, const int* __restrict__ btab,
    float* __restrict__ out)
{
    extern __shared__ char smem[];
    // ring: [slot][K/V][head][lane] float4
    float4 (*buf)[2][HD][32] = (float4(*)[2][HD][32])smem;
    int*      s_row  = (int*)(smem + SMEM_RING);          // 4 block rows
    unsigned* s_flag = (unsigned*)(smem + SMEM_RING + 16);

    const int split = blockIdx.x, b = blockIdx.y;
    const int tid = threadIdx.x;
    const int h = tid >> 5, lane = tid & 31;   // warp == head
    const int L  = ilen[b];
    const int s0 = split * CHUNK;

    if (s0 < L) {
        const int ntok = (L - s0 < CHUNK) ? (L - s0) : CHUNK;
        const int pos  = L - 1;                 // fresh-token position
        const int bh   = b * HD + h;

        // hoist block-table rows for this chunk (4 blocks of 16 tokens)
        if (tid < 4) s_row[tid] = __ldg(btab + b * MAXBD + (s0 >> 4) + tid);

        // --- RoPE on Q and K (registers, per-head per-warp) ---
        const float4 q4  = *(const float4*)(Q    + bh * DD + 4 * lane);
        const float4 k4  = *(const float4*)(K    + bh * DD + 4 * lane);
        const float4 vv4 = *(const float4*)(V    + bh * DD + 4 * lane);
        const float4 c4  = *(const float4*)(cosb + b * DD + 4 * lane);
        const float4 s4  = *(const float4*)(sinb + b * DD + 4 * lane);

        const float sgn = (lane < 16) ? -1.f : 1.f;   // rot = [-x2, x1]
        float4 qp, kp;
        qp.x = __shfl_xor_sync(~0u, q4.x, 16);  qp.y = __shfl_xor_sync(~0u, q4.y, 16);
        qp.z = __shfl_xor_sync(~0u, q4.z, 16);  qp.w = __shfl_xor_sync(~0u, q4.w, 16);
        kp.x = __shfl_xor_sync(~0u, k4.x, 16);  kp.y = __shfl_xor_sync(~0u, k4.y, 16);
        kp.z = __shfl_xor_sync(~0u, k4.z, 16);  kp.w = __shfl_xor_sync(~0u, k4.w, 16);

        float4 qr, kr;   // qr pre-scaled by softmax scale
        qr.x = (q4.x * c4.x + sgn * qp.x * s4.x) * SOFTMAX_SCALE;
        qr.y = (q4.y * c4.y + sgn * qp.y * s4.y) * SOFTMAX_SCALE;
        qr.z = (q4.z * c4.z + sgn * qp.z * s4.z) * SOFTMAX_SCALE;
        qr.w = (q4.w * c4.w + sgn * qp.w * s4.w) * SOFTMAX_SCALE;
        kr.x =  k4.x * c4.x + sgn * kp.x * s4.x;
        kr.y =  k4.y * c4.y + sgn * kp.y * s4.y;
        kr.z =  k4.z * c4.z + sgn * kp.z * s4.z;
        kr.w =  k4.w * c4.w + sgn * kp.w * s4.w;

        const float* mk = mask + b * MAXSD;

        __syncthreads();   // s_row visible before first issue

        // stage i: whole 8KB K row + 8KB V row of token s0+i (cooperative)
        auto issue = [&](int i) {
            if (i < ntok) {
                const int row = s_row[i >> 4] * BLKD + (i & 15);
                const size_t base = (size_t)row * (HD * DD);
                const int slot = i & (NSLOT - 1);
                cp16(&((float4*)buf[slot][0])[tid], (const float4*)(Kc + base) + tid);
                cp16(&((float4*)buf[slot][1])[tid], (const float4*)(Vc + base) + tid);
            }
            cp_commit();   // uniform group counting
        };
        issue(0); issue(1); issue(2);

        float m = NEGBIG, l = 0.f;
        float4 acc = make_float4(0.f, 0.f, 0.f, 0.f);

        for (int i = 0; i < ntok; i++) {
            cp_wait<2>();        // group i complete (2 stages stay in flight)
            __syncthreads();     // data visible; all warps done with slot (i-1)&3
            issue(i + 3);        // refill slot (i-1)&3 -- safe after barrier

            const int slot = i & (NSLOT - 1);
            const int t    = s0 + i;
            float4 kk = buf[slot][0][h][lane];
            float4 vv = buf[slot][1][h][lane];
            if (t == pos) { kk = kr; vv = vv4; }   // fresh token substitution

            float dot = qr.x * kk.x + qr.y * kk.y + qr.z * kk.z + qr.w * kk.w;
            #pragma unroll
            for (int o = 16; o > 0; o >>= 1)
                dot += __shfl_xor_sync(~0u, dot, o);

            const float score = dot + __ldg(mk + t);
            const float mnew  = fmaxf(m, score);
            const float corr  = __expf(m - mnew);
            const float p     = __expf(score - mnew);
            l = l * corr + p;
            acc.x = acc.x * corr + p * vv.x;
            acc.y = acc.y * corr + p * vv.y;
            acc.z = acc.z * corr + p * vv.z;
            acc.w = acc.w * corr + p * vv.w;
            m = mnew;
        }
        cp_wait<0>();   // drain trailing (empty) groups before smem reuse

        // per-warp partial straight to global scratch
        const int pidx = bh * NSPLIT + split;
        if (lane == 0) { g_pm[pidx] = m; g_pl[pidx] = l; }
        *(float4*)(g_pacc + pidx * DD + 4 * lane) = acc;
    }
    // empty splits write nothing: combiner uses ceil(L/CHUNK)

    // --- threadfence reduction: last split CTA for batch b combines ---
    __threadfence();
    __syncthreads();
    if (tid == 0)
        *s_flag = (atomicAdd(&g_cnt[b], 1u) == NSPLIT - 1u) ? 1u : 0u;
    __syncthreads();

    if (*s_flag) {
        const int nvalid = (L + CHUNK - 1) / CHUNK;   // valid splits for b
        const int d = tid & 127;       // dim
        const int g = tid >> 7;        // 0..3 head group
        #pragma unroll
        for (int it = 0; it < 4; it++) {
            const int hh   = g * 4 + it;
            const int base = (b * HD + hh) * NSPLIT;

            float M = NEGBIG;
            for (int i = 0; i < nvalid; i++) M = fmaxf(M, g_pm[base + i]);

            float Lt = 0.f, a = 0.f;
            for (int i = 0; i < nvalid; i++) {
                const float w = __expf(g_pm[base + i] - M);
                Lt += w * g_pl[base + i];
                a  += w * g_pacc[(base + i) * DD + d];
            }
            out[(b * HD + hh) * DD + d] = a / Lt;
        }
        if (tid == 0) g_cnt[b] = 0u;   // self-reset for next graph replay
    }
}

// ---------------------------------------------------------------------------
extern "C" void kernel_launch(void* const* d_in, const int* in_sizes, int n_in,
                              void* d_out, int out_size)
{
    const float* Q    = (const float*)d_in[0];
    const float* K    = (const float*)d_in[1];
    const float* V    = (const float*)d_in[2];
    const float* Kc   = (const float*)d_in[3];
    const float* Vc   = (const float*)d_in[4];
    const float* cosb = (const float*)d_in[5];
    const float* sinb = (const float*)d_in[6];
    const float* mask = (const float*)d_in[7];
    const int*   ilen = (const int*)d_in[8];
    // d_in[9] = save_slots — unused (fresh token is at input_length-1)
    const int*   btab = (const int*)d_in[10];
    (void)in_sizes; (void)n_in; (void)out_size;

    static int smem_set = 0;
    if (!smem_set) {
        cudaFuncSetAttribute(attn_fused,
                             cudaFuncAttributeMaxDynamicSharedMemorySize,
                             SMEM_TOTAL);
        smem_set = 1;
    }

    dim3 g1(NSPLIT, BD);
    attn_fused<<<g1, 512, SMEM_TOTAL>>>(Q, K, V, Kc, Vc, cosb, sinb, mask,
                                        ilen, btab, (float*)d_out);
}

// round 7
// speedup vs baseline: 1.5878x; 1.2898x over previous
#include <cuda_runtime.h>
#include <math.h>

// Problem constants (fixed by reference setup)
#define BD     16      // batch
#define HD     16      // heads
#define DD     128     // head dim
#define BLKD   16      // tokens per cache block
#define MAXBD  128     // blocks per sequence
#define MAXSD  2048    // max sequence length
#define NSPLIT 32      // token splits per batch
#define CHUNK  64      // tokens per split
#define SOFTMAX_SCALE 0.088388347648318447f  // 1/sqrt(128)
#define NEGBIG (-1e30f)

// Partial-result scratch (allocation-free: __device__ globals, zero-init .bss)
__device__ float g_pm[BD * HD * NSPLIT];
__device__ float g_pl[BD * HD * NSPLIT];
__device__ float g_pacc[BD * HD * NSPLIT * DD];      // 4 MB
__device__ unsigned int g_cnt[BD];                   // self-resetting counters

// ---------------------------------------------------------------------------
// Row-coherent split-KV decode attention.
//  grid (NSPLIT=32, BD): CTA = (64-token split, batch). 512 threads =
//  16 warps; warp w = head w. Every warp walks the SAME tokens (4 per
//  iteration, x4 unrolled, 8 independent float4 LDGs in flight) so the CTA's
//  concurrent loads tile complete 8KB K/V cache rows -> DRAM row-buffer
//  locality -- while keeping R3's barrier-free per-warp online-softmax
//  engine. Each warp produces a full (b,h,split) partial directly.
//  Fresh token (s == L-1) substitutes register-roped K / raw V.
//  Last split CTA per batch (threadfence reduction) combines
//  ceil(L/CHUNK) splits x 16 heads, writes out, resets counter
//  (graph-replay deterministic).
// ---------------------------------------------------------------------------
__global__ __launch_bounds__(512, 2) void attn_fused(
    const float* __restrict__ Q,  const float* __restrict__ K,
    const float* __restrict__ V,  const float* __restrict__ Kc,
    const float* __restrict__ Vc, const float* __restrict__ cosb,
    const float* __restrict__ sinb, const float* __restrict__ mask,
    const int* __restrict__ ilen, const int* __restrict__ btab,
    float* __restrict__ out)
{
    __shared__ unsigned s_flag;

    const int split = blockIdx.x, b = blockIdx.y;
    const int tid = threadIdx.x;
    const int h = tid >> 5, lane = tid & 31;   // warp == head
    const int L  = ilen[b];
    const int s0 = split * CHUNK;

    if (s0 < L) {
        const int s1  = (s0 + CHUNK < L) ? s0 + CHUNK : L;
        const int pos = L - 1;                 // fresh-token position
        const int bh  = b * HD + h;

        // --- RoPE on Q and K (registers, per-head per-warp) ---
        const float4 q4  = *(const float4*)(Q    + bh * DD + 4 * lane);
        const float4 k4  = *(const float4*)(K    + bh * DD + 4 * lane);
        const float4 vv4 = *(const float4*)(V    + bh * DD + 4 * lane);
        const float4 c4  = *(const float4*)(cosb + b * DD + 4 * lane);
        const float4 s4  = *(const float4*)(sinb + b * DD + 4 * lane);

        const float sgn = (lane < 16) ? -1.f : 1.f;   // rot = [-x2, x1]
        float4 qp, kp;
        qp.x = __shfl_xor_sync(~0u, q4.x, 16);  qp.y = __shfl_xor_sync(~0u, q4.y, 16);
        qp.z = __shfl_xor_sync(~0u, q4.z, 16);  qp.w = __shfl_xor_sync(~0u, q4.w, 16);
        kp.x = __shfl_xor_sync(~0u, k4.x, 16);  kp.y = __shfl_xor_sync(~0u, k4.y, 16);
        kp.z = __shfl_xor_sync(~0u, k4.z, 16);  kp.w = __shfl_xor_sync(~0u, k4.w, 16);

        float4 qr, kr;   // qr pre-scaled by softmax scale
        qr.x = (q4.x * c4.x + sgn * qp.x * s4.x) * SOFTMAX_SCALE;
        qr.y = (q4.y * c4.y + sgn * qp.y * s4.y) * SOFTMAX_SCALE;
        qr.z = (q4.z * c4.z + sgn * qp.z * s4.z) * SOFTMAX_SCALE;
        qr.w = (q4.w * c4.w + sgn * qp.w * s4.w) * SOFTMAX_SCALE;
        kr.x =  k4.x * c4.x + sgn * kp.x * s4.x;
        kr.y =  k4.y * c4.y + sgn * kp.y * s4.y;
        kr.z =  k4.z * c4.z + sgn * kp.z * s4.z;
        kr.w =  k4.w * c4.w + sgn * kp.w * s4.w;

        const int*   bt = btab + b * MAXBD;
        const float* mk = mask + b * MAXSD;

        float m = NEGBIG, l = 0.f;
        float4 acc = make_float4(0.f, 0.f, 0.f, 0.f);

        const int niter = (s1 - s0 + 3) >> 2;   // groups of 4 tokens
        for (int k = 0; k < niter; k++) {
            const int tb = s0 + 4 * k;

            // 8 independent float4 loads (4 tokens x K,V). Tokens beyond s1
            // are safe loads (every cache row exists) and get p=0 below.
            float4 kk[4], vv[4];
            #pragma unroll
            for (int j = 0; j < 4; j++) {
                const int t   = tb + j;                       // < MAXSD always
                const int row = __ldg(bt + (t >> 4)) * BLKD + (t & 15);
                const int off = (row * HD + h) * DD + 4 * lane;
                const bool sp = (t == pos);
                kk[j] = sp ? kr  : __ldg((const float4*)(Kc + off));
                vv[j] = sp ? vv4 : __ldg((const float4*)(Vc + off));
            }
            float dot[4];
            #pragma unroll
            for (int j = 0; j < 4; j++)
                dot[j] = qr.x * kk[j].x + qr.y * kk[j].y
                       + qr.z * kk[j].z + qr.w * kk[j].w;
            #pragma unroll
            for (int o = 16; o > 0; o >>= 1) {
                #pragma unroll
                for (int j = 0; j < 4; j++)
                    dot[j] += __shfl_xor_sync(~0u, dot[j], o);
            }
            float sc[4];
            #pragma unroll
            for (int j = 0; j < 4; j++) {
                const int t = tb + j;
                sc[j] = (t < s1) ? dot[j] + __ldg(mk + t) : NEGBIG;
            }
            const float gm   = fmaxf(fmaxf(sc[0], sc[1]), fmaxf(sc[2], sc[3]));
            const float mnew = fmaxf(m, gm);
            const float corr = __expf(m - mnew);
            float p[4];
            #pragma unroll
            for (int j = 0; j < 4; j++) {
                p[j] = __expf(sc[j] - mnew);
                if (tb + j >= s1) p[j] = 0.f;
            }
            l = l * corr + ((p[0] + p[1]) + (p[2] + p[3]));
            acc.x = acc.x * corr + (p[0]*vv[0].x + p[1]*vv[1].x + p[2]*vv[2].x + p[3]*vv[3].x);
            acc.y = acc.y * corr + (p[0]*vv[0].y + p[1]*vv[1].y + p[2]*vv[2].y + p[3]*vv[3].y);
            acc.z = acc.z * corr + (p[0]*vv[0].z + p[1]*vv[1].z + p[2]*vv[2].z + p[3]*vv[3].z);
            acc.w = acc.w * corr + (p[0]*vv[0].w + p[1]*vv[1].w + p[2]*vv[2].w + p[3]*vv[3].w);
            m = mnew;
        }

        // warp partial = complete (b,h,split) partial -> global scratch
        const int pidx = bh * NSPLIT + split;
        if (lane == 0) { g_pm[pidx] = m; g_pl[pidx] = l; }
        *(float4*)(g_pacc + pidx * DD + 4 * lane) = acc;
    }
    // empty splits write nothing: combiner uses ceil(L/CHUNK)

    // --- threadfence reduction: last split CTA for batch b combines ---
    __threadfence();
    __syncthreads();
    if (tid == 0)
        s_flag = (atomicAdd(&g_cnt[b], 1u) == NSPLIT - 1u) ? 1u : 0u;
    __syncthreads();

    if (s_flag) {
        const int nvalid = (L + CHUNK - 1) / CHUNK;   // valid splits for b
        const int d = tid & 127;       // dim
        const int g = tid >> 7;        // 0..3 head group
        #pragma unroll
        for (int it = 0; it < 4; it++) {
            const int hh   = g * 4 + it;
            const int base = (b * HD + hh) * NSPLIT;

            float M = NEGBIG;
            for (int i = 0; i < nvalid; i++) M = fmaxf(M, g_pm[base + i]);

            float Lt = 0.f, a = 0.f;
            for (int i = 0; i < nvalid; i++) {
                const float w = __expf(g_pm[base + i] - M);
                Lt += w * g_pl[base + i];
                a  += w * g_pacc[(base + i) * DD + d];
            }
            out[(b * HD + hh) * DD + d] = a / Lt;
        }
        if (tid == 0) g_cnt[b] = 0u;   // self-reset for next graph replay
    }
}

// ---------------------------------------------------------------------------
extern "C" void kernel_launch(void* const* d_in, const int* in_sizes, int n_in,
                              void* d_out, int out_size)
{
    const float* Q    = (const float*)d_in[0];
    const float* K    = (const float*)d_in[1];
    const float* V    = (const float*)d_in[2];
    const float* Kc   = (const float*)d_in[3];
    const float* Vc   = (const float*)d_in[4];
    const float* cosb = (const float*)d_in[5];
    const float* sinb = (const float*)d_in[6];
    const float* mask = (const float*)d_in[7];
    const int*   ilen = (const int*)d_in[8];
    // d_in[9] = save_slots — unused (fresh token is at input_length-1)
    const int*   btab = (const int*)d_in[10];
    (void)in_sizes; (void)n_in; (void)out_size;

    dim3 g1(NSPLIT, BD);
    attn_fused<<<g1, 512>>>(Q, K, V, Kc, Vc, cosb, sinb, mask, ilen, btab,
                            (float*)d_out);
}

// round 9
// speedup vs baseline: 1.8211x; 1.1469x over previous
#include <cuda_runtime.h>
#include <math.h>

// Problem constants (fixed by reference setup)
#define BD     16      // batch
#define HD     16      // heads
#define DD     128     // head dim
#define BLKD   16      // tokens per cache block
#define MAXBD  128     // blocks per sequence
#define MAXSD  2048    // max sequence length
#define NSPLIT 16      // token splits per (b,h)
#define CHUNK  128     // tokens per split
#define WTOK   32      // contiguous tokens per warp
#define SOFTMAX_SCALE 0.088388347648318447f  // 1/sqrt(128)
#define NEGBIG (-1e30f)

// Partial-result scratch (allocation-free: __device__ globals, zero-init .bss)
__device__ float g_pm[BD * HD * NSPLIT];
__device__ float g_pl[BD * HD * NSPLIT];
__device__ float g_pacc[BD * HD * NSPLIT * DD];      // 2 MB
__device__ unsigned int g_cnt[BD * HD];              // self-resetting counters

// ---------------------------------------------------------------------------
// Split-KV decode attention, btab-hoisted.
//  grid (NSPLIT, HD, BD), 128 threads = 4 warps.
//  Warp w owns CONTIGUOUS tokens [s0+32w, s0+32w+32): it needs exactly two
//  block-table entries, loaded ONCE before the loop. The token loop's K/V
//  addresses are then pure register arithmetic -> all 8 float4 LDGs per
//  4-token iteration issue back-to-back with no dependent L2 hop, and the
//  4 rows touched are consecutive (two contiguous 2KB runs).
//  Fresh token (s == L-1) substitutes register-roped K / raw V.
//  Last split CTA per (b,h) (threadfence reduction) combines partials,
//  writes output, resets its counter (graph-replay deterministic).
// ---------------------------------------------------------------------------
__global__ __launch_bounds__(128, 8) void attn_fused(
    const float* __restrict__ Q,  const float* __restrict__ K,
    const float* __restrict__ V,  const float* __restrict__ Kc,
    const float* __restrict__ Vc, const float* __restrict__ cosb,
    const float* __restrict__ sinb, const float* __restrict__ mask,
    const int* __restrict__ ilen, const int* __restrict__ btab,
    float* __restrict__ out)
{
    const int split = blockIdx.x, h = blockIdx.y, b = blockIdx.z;
    const int tid = threadIdx.x, warp = tid >> 5, lane = tid & 31;
    const int bh   = b * HD + h;
    const int pidx = bh * NSPLIT + split;
    const int L  = ilen[b];
    const int s0 = split * CHUNK;

    if (s0 < L) {
        const int s1  = (s0 + CHUNK < L) ? s0 + CHUNK : L;
        const int pos = L - 1;   // fresh-token position

        // --- RoPE on Q and K (registers) ---
        const float4 q4  = *(const float4*)(Q    + bh * DD + 4 * lane);
        const float4 k4  = *(const float4*)(K    + bh * DD + 4 * lane);
        const float4 vv4 = *(const float4*)(V    + bh * DD + 4 * lane);
        const float4 c4  = *(const float4*)(cosb + b * DD + 4 * lane);
        const float4 s4  = *(const float4*)(sinb + b * DD + 4 * lane);

        const float sgn = (lane < 16) ? -1.f : 1.f;   // rot = [-x2, x1]
        float4 qp, kp;
        qp.x = __shfl_xor_sync(~0u, q4.x, 16);  qp.y = __shfl_xor_sync(~0u, q4.y, 16);
        qp.z = __shfl_xor_sync(~0u, q4.z, 16);  qp.w = __shfl_xor_sync(~0u, q4.w, 16);
        kp.x = __shfl_xor_sync(~0u, k4.x, 16);  kp.y = __shfl_xor_sync(~0u, k4.y, 16);
        kp.z = __shfl_xor_sync(~0u, k4.z, 16);  kp.w = __shfl_xor_sync(~0u, k4.w, 16);

        float4 qr, kr;   // qr pre-scaled by softmax scale
        qr.x = (q4.x * c4.x + sgn * qp.x * s4.x) * SOFTMAX_SCALE;
        qr.y = (q4.y * c4.y + sgn * qp.y * s4.y) * SOFTMAX_SCALE;
        qr.z = (q4.z * c4.z + sgn * qp.z * s4.z) * SOFTMAX_SCALE;
        qr.w = (q4.w * c4.w + sgn * qp.w * s4.w) * SOFTMAX_SCALE;
        kr.x =  k4.x * c4.x + sgn * kp.x * s4.x;
        kr.y =  k4.y * c4.y + sgn * kp.y * s4.y;
        kr.z =  k4.z * c4.z + sgn * kp.z * s4.z;
        kr.w =  k4.w * c4.w + sgn * kp.w * s4.w;

        const float* mk  = mask + b * MAXSD;
        const int    ws0 = s0 + WTOK * warp;          // warp's first token

        float m = NEGBIG, l = 0.f;
        float4 acc = make_float4(0.f, 0.f, 0.f, 0.f);

        if (ws0 < s1) {
            // hoist the warp's two block-table entries (tokens ws0..ws0+31)
            const int* bt = btab + b * MAXBD;
            const int  e0 = __ldg(bt + (ws0 >> 4));
            const int  e1 = __ldg(bt + (ws0 >> 4) + 1);

            #pragma unroll
            for (int k = 0; k < WTOK / 4; k++) {
                const int tb = ws0 + 4 * k;           // 4 consecutive tokens
                if (tb >= s1) break;                  // warp-uniform exit

                // rows: same 16-block for all 4 (tb&15 in {0,4,8,12})
                const int e    = (k < 4) ? e0 : e1;
                const int row0 = e * BLKD + (tb & 15);
                const int off0 = (row0 * HD + h) * DD + 4 * lane;

                float4 kk[4], vv[4];
                #pragma unroll
                for (int j = 0; j < 4; j++) {
                    const int  off = off0 + j * (HD * DD);
                    const bool sp  = (tb + j == pos);
                    kk[j] = sp ? kr  : __ldg((const float4*)(Kc + off));
                    vv[j] = sp ? vv4 : __ldg((const float4*)(Vc + off));
                }
                const float4 mk4 = __ldg((const float4*)(mk + tb)); // uniform

                float dot[4];
                #pragma unroll
                for (int j = 0; j < 4; j++)
                    dot[j] = qr.x * kk[j].x + qr.y * kk[j].y
                           + qr.z * kk[j].z + qr.w * kk[j].w;
                #pragma unroll
                for (int o = 16; o > 0; o >>= 1) {
                    #pragma unroll
                    for (int j = 0; j < 4; j++)
                        dot[j] += __shfl_xor_sync(~0u, dot[j], o);
                }
                float sc[4];
                sc[0] = (tb     < s1) ? dot[0] + mk4.x : NEGBIG;
                sc[1] = (tb + 1 < s1) ? dot[1] + mk4.y : NEGBIG;
                sc[2] = (tb + 2 < s1) ? dot[2] + mk4.z : NEGBIG;
                sc[3] = (tb + 3 < s1) ? dot[3] + mk4.w : NEGBIG;

                const float gm   = fmaxf(fmaxf(sc[0], sc[1]), fmaxf(sc[2], sc[3]));
                const float mnew = fmaxf(m, gm);
                const float corr = __expf(m - mnew);
                float p[4];
                #pragma unroll
                for (int j = 0; j < 4; j++) {
                    p[j] = __expf(sc[j] - mnew);
                    if (tb + j >= s1) p[j] = 0.f;
                }
                l = l * corr + ((p[0] + p[1]) + (p[2] + p[3]));
                acc.x = acc.x * corr + (p[0]*vv[0].x + p[1]*vv[1].x + p[2]*vv[2].x + p[3]*vv[3].x);
                acc.y = acc.y * corr + (p[0]*vv[0].y + p[1]*vv[1].y + p[2]*vv[2].y + p[3]*vv[3].y);
                acc.z = acc.z * corr + (p[0]*vv[0].z + p[1]*vv[1].z + p[2]*vv[2].z + p[3]*vv[3].z);
                acc.w = acc.w * corr + (p[0]*vv[0].w + p[1]*vv[1].w + p[2]*vv[2].w + p[3]*vv[3].w);
                m = mnew;
            }
        }

        // --- combine the 4 warps' partials ---
        __shared__ float sm_m[4], sm_l[4], sm_a[4 * DD];
        float* dst = sm_a + warp * DD + 4 * lane;
        dst[0] = acc.x; dst[1] = acc.y; dst[2] = acc.z; dst[3] = acc.w;
        if (lane == 0) { sm_m[warp] = m; sm_l[warp] = l; }
        __syncthreads();

        const float M = fmaxf(fmaxf(sm_m[0], sm_m[1]), fmaxf(sm_m[2], sm_m[3]));
        float Lt = 0.f, a = 0.f;
        #pragma unroll
        for (int w = 0; w < 4; w++) {
            const float wl = sm_l[w];
            const float wf = (wl > 0.f) ? __expf(sm_m[w] - M) : 0.f;
            Lt += wf * wl;
            a  += wf * sm_a[w * DD + tid];
        }
        if (tid == 0) { g_pm[pidx] = M; g_pl[pidx] = Lt; }
        g_pacc[pidx * DD + tid] = a;
    } else {
        // empty split: neutral partial
        if (tid == 0) { g_pm[pidx] = NEGBIG; g_pl[pidx] = 0.f; }
        g_pacc[pidx * DD + tid] = 0.f;
    }

    // --- threadfence reduction: last split CTA combines & writes output ---
    __shared__ unsigned s_last;
    __threadfence();
    __syncthreads();
    if (tid == 0)
        s_last = (atomicAdd(&g_cnt[bh], 1u) == NSPLIT - 1u) ? 1u : 0u;
    __syncthreads();

    if (s_last) {
        const int base = bh * NSPLIT;
        float M = -INFINITY;
        #pragma unroll
        for (int i = 0; i < NSPLIT; i++)
            if (g_pl[base + i] > 0.f) M = fmaxf(M, g_pm[base + i]);

        float Lt = 0.f, a = 0.f;
        #pragma unroll
        for (int i = 0; i < NSPLIT; i++) {
            const float li = g_pl[base + i];
            if (li > 0.f) {
                const float w = __expf(g_pm[base + i] - M);
                Lt += w * li;
                a  += w * g_pacc[(base + i) * DD + tid];
            }
        }
        out[bh * DD + tid] = a / Lt;
        if (tid == 0) g_cnt[bh] = 0u;   // self-reset for next graph replay
    }
}

// ---------------------------------------------------------------------------
extern "C" void kernel_launch(void* const* d_in, const int* in_sizes, int n_in,
                              void* d_out, int out_size)
{
    const float* Q    = (const float*)d_in[0];
    const float* K    = (const float*)d_in[1];
    const float* V    = (const float*)d_in[2];
    const float* Kc   = (const float*)d_in[3];
    const float* Vc   = (const float*)d_in[4];
    const float* cosb = (const float*)d_in[5];
    const float* sinb = (const float*)d_in[6];
    const float* mask = (const float*)d_in[7];
    const int*   ilen = (const int*)d_in[8];
    // d_in[9] = save_slots — unused (fresh token is at input_length-1)
    const int*   btab = (const int*)d_in[10];
    (void)in_sizes; (void)n_in; (void)out_size;

    dim3 g1(NSPLIT, HD, BD);
    attn_fused<<<g1, 128>>>(Q, K, V, Kc, Vc, cosb, sinb, mask, ilen, btab,
                            (float*)d_out);
}

// round 10
// speedup vs baseline: 1.9807x; 1.0876x over previous
#include <cuda_runtime.h>
#include <math.h>

// Problem constants (fixed by reference setup)
#define BD     16      // batch
#define HD     16      // heads
#define DD     128     // head dim
#define BLKD   16      // tokens per cache block
#define MAXBD  128     // blocks per sequence
#define MAXSD  2048    // max sequence length
#define NSPLIT 16      // token splits per (b,h)
#define CHUNK  128     // tokens per split
#define WTOK   32      // contiguous tokens per warp
#define SOFTMAX_SCALE 0.088388347648318447f  // 1/sqrt(128)
#define NEGBIG (-1e30f)

// Partial-result scratch (allocation-free: __device__ globals, zero-init .bss)
__device__ float g_pm[BD * HD * NSPLIT];
__device__ float g_pl[BD * HD * NSPLIT];
__device__ float g_pacc[BD * HD * NSPLIT * DD];      // 2 MB
__device__ unsigned int g_cnt[BD * HD];              // self-resetting counters

// ---------------------------------------------------------------------------
// Split-KV decode attention, btab-hoisted + streaming loads + lean empties.
//  grid (NSPLIT, HD, BD), 128 threads = 4 warps.
//  Warp w owns CONTIGUOUS tokens [s0+32w, s0+32w+32): two block-table
//  entries loaded once before the loop; K/V addresses are pure register
//  arithmetic; 8 float4 LDGs per 4-token iteration issue back-to-back.
//  KV loads use __ldcs (evict-first): the 262MB stream has zero reuse and
//  should not thrash L2 residency of btab/mask/Q/partials.
//  EMPTY splits (s0 >= L) write NO scratch: the combiner derives
//  nvalid = ceil(L/CHUNK) and reads only those partials.
//  Fresh token (s == L-1) substitutes register-roped K / raw V.
//  Last split CTA per (b,h) (threadfence reduction) combines nvalid
//  partials, writes output, resets its counter (graph-replay deterministic).
// ---------------------------------------------------------------------------
__global__ __launch_bounds__(128, 8) void attn_fused(
    const float* __restrict__ Q,  const float* __restrict__ K,
    const float* __restrict__ V,  const float* __restrict__ Kc,
    const float* __restrict__ Vc, const float* __restrict__ cosb,
    const float* __restrict__ sinb, const float* __restrict__ mask,
    const int* __restrict__ ilen, const int* __restrict__ btab,
    float* __restrict__ out)
{
    const int split = blockIdx.x, h = blockIdx.y, b = blockIdx.z;
    const int tid = threadIdx.x, warp = tid >> 5, lane = tid & 31;
    const int bh   = b * HD + h;
    const int pidx = bh * NSPLIT + split;
    const int L  = ilen[b];
    const int s0 = split * CHUNK;

    if (s0 < L) {
        const int s1  = (s0 + CHUNK < L) ? s0 + CHUNK : L;
        const int pos = L - 1;   // fresh-token position

        // --- RoPE on Q and K (registers) ---
        const float4 q4  = *(const float4*)(Q    + bh * DD + 4 * lane);
        const float4 k4  = *(const float4*)(K    + bh * DD + 4 * lane);
        const float4 vv4 = *(const float4*)(V    + bh * DD + 4 * lane);
        const float4 c4  = *(const float4*)(cosb + b * DD + 4 * lane);
        const float4 s4  = *(const float4*)(sinb + b * DD + 4 * lane);

        const float sgn = (lane < 16) ? -1.f : 1.f;   // rot = [-x2, x1]
        float4 qp, kp;
        qp.x = __shfl_xor_sync(~0u, q4.x, 16);  qp.y = __shfl_xor_sync(~0u, q4.y, 16);
        qp.z = __shfl_xor_sync(~0u, q4.z, 16);  qp.w = __shfl_xor_sync(~0u, q4.w, 16);
        kp.x = __shfl_xor_sync(~0u, k4.x, 16);  kp.y = __shfl_xor_sync(~0u, k4.y, 16);
        kp.z = __shfl_xor_sync(~0u, k4.z, 16);  kp.w = __shfl_xor_sync(~0u, k4.w, 16);

        float4 qr, kr;   // qr pre-scaled by softmax scale
        qr.x = (q4.x * c4.x + sgn * qp.x * s4.x) * SOFTMAX_SCALE;
        qr.y = (q4.y * c4.y + sgn * qp.y * s4.y) * SOFTMAX_SCALE;
        qr.z = (q4.z * c4.z + sgn * qp.z * s4.z) * SOFTMAX_SCALE;
        qr.w = (q4.w * c4.w + sgn * qp.w * s4.w) * SOFTMAX_SCALE;
        kr.x =  k4.x * c4.x + sgn * kp.x * s4.x;
        kr.y =  k4.y * c4.y + sgn * kp.y * s4.y;
        kr.z =  k4.z * c4.z + sgn * kp.z * s4.z;
        kr.w =  k4.w * c4.w + sgn * kp.w * s4.w;

        const float* mk  = mask + b * MAXSD;
        const int    ws0 = s0 + WTOK * warp;          // warp's first token

        float m = NEGBIG, l = 0.f;
        float4 acc = make_float4(0.f, 0.f, 0.f, 0.f);

        if (ws0 < s1) {
            // hoist the warp's two block-table entries (tokens ws0..ws0+31)
            const int* bt = btab + b * MAXBD;
            const int  e0 = __ldg(bt + (ws0 >> 4));
            const int  e1 = __ldg(bt + (ws0 >> 4) + 1);

            #pragma unroll
            for (int k = 0; k < WTOK / 4; k++) {
                const int tb = ws0 + 4 * k;           // 4 consecutive tokens
                if (tb >= s1) break;                  // warp-uniform exit

                // rows: same 16-block for all 4 (tb&15 in {0,4,8,12})
                const int e    = (k < 4) ? e0 : e1;
                const int row0 = e * BLKD + (tb & 15);
                const int off0 = (row0 * HD + h) * DD + 4 * lane;

                float4 kk[4], vv[4];
                #pragma unroll
                for (int j = 0; j < 4; j++) {
                    const int  off = off0 + j * (HD * DD);
                    const bool sp  = (tb + j == pos);
                    kk[j] = sp ? kr  : __ldcs((const float4*)(Kc + off));
                    vv[j] = sp ? vv4 : __ldcs((const float4*)(Vc + off));
                }
                const float4 mk4 = __ldg((const float4*)(mk + tb)); // uniform

                float dot[4];
                #pragma unroll
                for (int j = 0; j < 4; j++)
                    dot[j] = qr.x * kk[j].x + qr.y * kk[j].y
                           + qr.z * kk[j].z + qr.w * kk[j].w;
                #pragma unroll
                for (int o = 16; o > 0; o >>= 1) {
                    #pragma unroll
                    for (int j = 0; j < 4; j++)
                        dot[j] += __shfl_xor_sync(~0u, dot[j], o);
                }
                float sc[4];
                sc[0] = (tb     < s1) ? dot[0] + mk4.x : NEGBIG;
                sc[1] = (tb + 1 < s1) ? dot[1] + mk4.y : NEGBIG;
                sc[2] = (tb + 2 < s1) ? dot[2] + mk4.z : NEGBIG;
                sc[3] = (tb + 3 < s1) ? dot[3] + mk4.w : NEGBIG;

                const float gm   = fmaxf(fmaxf(sc[0], sc[1]), fmaxf(sc[2], sc[3]));
                const float mnew = fmaxf(m, gm);
                const float corr = __expf(m - mnew);
                float p[4];
                #pragma unroll
                for (int j = 0; j < 4; j++) {
                    p[j] = __expf(sc[j] - mnew);
                    if (tb + j >= s1) p[j] = 0.f;
                }
                l = l * corr + ((p[0] + p[1]) + (p[2] + p[3]));
                acc.x = acc.x * corr + (p[0]*vv[0].x + p[1]*vv[1].x + p[2]*vv[2].x + p[3]*vv[3].x);
                acc.y = acc.y * corr + (p[0]*vv[0].y + p[1]*vv[1].y + p[2]*vv[2].y + p[3]*vv[3].y);
                acc.z = acc.z * corr + (p[0]*vv[0].z + p[1]*vv[1].z + p[2]*vv[2].z + p[3]*vv[3].z);
                acc.w = acc.w * corr + (p[0]*vv[0].w + p[1]*vv[1].w + p[2]*vv[2].w + p[3]*vv[3].w);
                m = mnew;
            }
        }

        // --- combine the 4 warps' partials ---
        __shared__ float sm_m[4], sm_l[4], sm_a[4 * DD];
        float* dst = sm_a + warp * DD + 4 * lane;
        dst[0] = acc.x; dst[1] = acc.y; dst[2] = acc.z; dst[3] = acc.w;
        if (lane == 0) { sm_m[warp] = m; sm_l[warp] = l; }
        __syncthreads();

        const float M = fmaxf(fmaxf(sm_m[0], sm_m[1]), fmaxf(sm_m[2], sm_m[3]));
        float Lt = 0.f, a = 0.f;
        #pragma unroll
        for (int w = 0; w < 4; w++) {
            const float wl = sm_l[w];
            const float wf = (wl > 0.f) ? __expf(sm_m[w] - M) : 0.f;
            Lt += wf * wl;
            a  += wf * sm_a[w * DD + tid];
        }
        if (tid == 0) { g_pm[pidx] = M; g_pl[pidx] = Lt; }
        g_pacc[pidx * DD + tid] = a;
    }
    // empty splits write NOTHING: combiner uses nvalid = ceil(L/CHUNK)

    // --- threadfence reduction: last split CTA combines & writes output ---
    __shared__ unsigned s_last;
    __threadfence();
    __syncthreads();
    if (tid == 0)
        s_last = (atomicAdd(&g_cnt[bh], 1u) == NSPLIT - 1u) ? 1u : 0u;
    __syncthreads();

    if (s_last) {
        const int nvalid = (L + CHUNK - 1) / CHUNK;   // valid splits for bh
        const int base   = bh * NSPLIT;

        float M = NEGBIG;
        for (int i = 0; i < nvalid; i++) M = fmaxf(M, g_pm[base + i]);

        float Lt = 0.f, a = 0.f;
        for (int i = 0; i < nvalid; i++) {
            const float w = __expf(g_pm[base + i] - M);
            Lt += w * g_pl[base + i];
            a  += w * g_pacc[(base + i) * DD + tid];
        }
        out[bh * DD + tid] = a / Lt;
        if (tid == 0) g_cnt[bh] = 0u;   // self-reset for next graph replay
    }
}

// ---------------------------------------------------------------------------
extern "C" void kernel_launch(void* const* d_in, const int* in_sizes, int n_in,
                              void* d_out, int out_size)
{
    const float* Q    = (const float*)d_in[0];
    const float* K    = (const float*)d_in[1];
    const float* V    = (const float*)d_in[2];
    const float* Kc   = (const float*)d_in[3];
    const float* Vc   = (const float*)d_in[4];
    const float* cosb = (const float*)d_in[5];
    const float* sinb = (const float*)d_in[6];
    const float* mask = (const float*)d_in[7];
    const int*   ilen = (const int*)d_in[8];
    // d_in[9] = save_slots — unused (fresh token is at input_length-1)
    const int*   btab = (const int*)d_in[10];
    (void)in_sizes; (void)n_in; (void)out_size;

    dim3 g1(NSPLIT, HD, BD);
    attn_fused<<<g1, 128>>>(Q, K, V, Kc, Vc, cosb, sinb, mask, ilen, btab,
                            (float*)d_out);
}